// round 5
// baseline (speedup 1.0000x reference)
#include <cuda_runtime.h>

// TimeSeriesWineSNN: 3-layer LIF SNN, T sequential steps, B=4096.
// I=8 -> H1=28 -> H2=8 -> O=4. beta=0.9, thr=1.0 (subtract reset).
// Outputs: mem3, spk3, spk1, spk2, each [T,B,C].
//
// 8 lanes per batch element (32768 threads). Spike exchange via BALLOT
// (1 bit/spike) instead of shuffles: bit (8*oct + j) of ballot_p holds
// channel (4j+p) of the octet's element.
//
// PROTECTED NUMERICS (validated r4, rel_err 4.4e-9):
//  * products rounded separately: p_k = __fmul_rn(s_k, w_k)  (no fma)
//    -> for s in {0,1}: select w_k or 0 (bit-exact; zero-sign dies at bias add)
//  * width-8 tree:  ((p0+p4)+(p2+p6)) + ((p1+p5)+(p3+p7))
//  * width-28 tree: 32-lane tree with zero padding (tree28 below)
//  * epilogue: m = fma(beta, m_prev, dot + b) - s_prev ; s = (m > 1)

constexpr int   Bb  = 4096;
constexpr int   Ii  = 8;
constexpr int   H1  = 28;
constexpr int   H2  = 8;
constexpr int   Oo  = 4;
constexpr float BETA = 0.9f;
constexpr float THR  = 1.0f;

__device__ __forceinline__ float tree8(const float* __restrict__ p) {
    float a = __fadd_rn(__fadd_rn(p[0], p[4]), __fadd_rn(p[2], p[6]));
    float b = __fadd_rn(__fadd_rn(p[1], p[5]), __fadd_rn(p[3], p[7]));
    return __fadd_rn(a, b);
}

// 32-lane shfl-tree over p[0..27], p[28..31]=0 (zero adds exact)
__device__ __forceinline__ float tree28(const float* __restrict__ p) {
    float r[8];
    #pragma unroll
    for (int i = 0; i < 4; ++i)
        r[i] = __fadd_rn(__fadd_rn(p[i], p[i + 16]),
                         __fadd_rn(p[i + 8], p[i + 24]));
    #pragma unroll
    for (int i = 4; i < 8; ++i)
        r[i] = __fadd_rn(__fadd_rn(p[i], p[i + 16]), p[i + 8]);
    float s0 = __fadd_rn(r[0], r[4]);
    float s1 = __fadd_rn(r[1], r[5]);
    float s2 = __fadd_rn(r[2], r[6]);
    float s3 = __fadd_rn(r[3], r[7]);
    return __fadd_rn(__fadd_rn(s0, s2), __fadd_rn(s1, s3));
}

__global__ void __launch_bounds__(32)
snn_kernel(const float* __restrict__ x,
           const float* __restrict__ W1, const float* __restrict__ b1,
           const float* __restrict__ W2, const float* __restrict__ b2,
           const float* __restrict__ W3, const float* __restrict__ b3,
           float* __restrict__ out_mem3, float* __restrict__ out_spk3,
           float* __restrict__ out_spk1, float* __restrict__ out_spk2,
           int T)
{
    const int tid  = blockIdx.x * 32 + threadIdx.x;
    const int lane = tid & 7;                 // lane within octet
    const int oct  = (threadIdx.x >> 3) & 3;  // octet within warp
    const int b    = tid >> 3;                // batch element
    if (b >= Bb) return;

    // ---- weights into registers (padded layer-1 channels get w=0,b=0) ----
    float w1[4][8], b1r[4];
    #pragma unroll
    for (int p = 0; p < 4; ++p) {
        const int c = 4 * lane + p;
        const bool real = (c < H1);
        b1r[p] = real ? b1[c] : 0.0f;
        #pragma unroll
        for (int k = 0; k < Ii; ++k)
            w1[p][k] = real ? W1[c * Ii + k] : 0.0f;
    }
    float w2[H1], b2r;
    {
        const int c = lane;
        b2r = b2[c];
        #pragma unroll
        for (int k = 0; k < H1; ++k) w2[k] = W2[c * H1 + k];
    }
    float w3[H2], b3r;
    {
        const int c = (lane < Oo) ? lane : 0;
        b3r = b3[c];
        #pragma unroll
        for (int k = 0; k < H2; ++k) w3[k] = W3[c * H2 + k];
    }

    // ---- state ----
    float m1[4] = {0.f, 0.f, 0.f, 0.f};
    float s1f[4] = {0.f, 0.f, 0.f, 0.f};
    float m2 = 0.f, s2f = 0.f, m3 = 0.f, s3f = 0.f;

    // ---- pointers ----
    const size_t sX  = (size_t)Bb * Ii;
    const size_t st1 = (size_t)Bb * H1;
    const size_t st2 = (size_t)Bb * H2;
    const size_t st3 = (size_t)Bb * Oo;

    const float* px = x + (size_t)b * Ii;
    float* p1 = out_spk1 + (size_t)b * H1 + 4 * lane;   // 16B aligned
    float* p2 = out_spk2 + (size_t)b * H2 + lane;
    float* p3 = out_spk3 + (size_t)b * Oo + lane;
    float* pm = out_mem3 + (size_t)b * Oo + lane;

    float4 xa = *(const float4*)px;
    float4 xb = *(const float4*)(px + 4);

    #pragma unroll 2
    for (int t = 0; t < T; ++t) {
        const float* pn = px + ((t + 1 < T) ? sX : 0);
        const float4 nxa = *(const float4*)pn;
        const float4 nxb = *(const float4*)(pn + 4);
        px = pn;

        const float xk[8] = {xa.x, xa.y, xa.z, xa.w, xb.x, xb.y, xb.z, xb.w};

        // ---------- layer 1 ----------
        bool sp1[4];
        #pragma unroll
        for (int p = 0; p < 4; ++p) {
            float pr[8];
            #pragma unroll
            for (int k = 0; k < Ii; ++k) pr[k] = __fmul_rn(xk[k], w1[p][k]);
            float a = __fadd_rn(tree8(pr), b1r[p]);
            m1[p]  = __fsub_rn(__fmaf_rn(BETA, m1[p], a), s1f[p]);
            sp1[p] = (m1[p] > THR);
            s1f[p] = sp1[p] ? 1.0f : 0.0f;
        }
        if (lane < 7)
            *(float4*)p1 = make_float4(s1f[0], s1f[1], s1f[2], s1f[3]);

        // ---------- spike all-gather via ballot (bit 8*oct+j = ch 4j+p) ----
        unsigned bb[4];
        #pragma unroll
        for (int p = 0; p < 4; ++p)
            bb[p] = (__ballot_sync(0xffffffffu, sp1[p]) >> (oct * 8)) & 0xffu;

        // ---------- layer 2 : masked products, 28-wide tree ----------
        bool sp2;
        {
            float pr[H1];
            #pragma unroll
            for (int j = 0; j < 7; ++j)
                #pragma unroll
                for (int p = 0; p < 4; ++p)
                    pr[4 * j + p] = ((bb[p] >> j) & 1u) ? w2[4 * j + p] : 0.0f;
            float a = __fadd_rn(tree28(pr), b2r);
            m2  = __fsub_rn(__fmaf_rn(BETA, m2, a), s2f);
            sp2 = (m2 > THR);
            s2f = sp2 ? 1.0f : 0.0f;
        }
        *p2 = s2f;

        const unsigned b2b = (__ballot_sync(0xffffffffu, sp2) >> (oct * 8)) & 0xffu;

        // ---------- layer 3 : masked products, 8-wide tree ----------
        {
            float pr[H2];
            #pragma unroll
            for (int k = 0; k < H2; ++k)
                pr[k] = ((b2b >> k) & 1u) ? w3[k] : 0.0f;
            float a = __fadd_rn(tree8(pr), b3r);
            m3  = __fsub_rn(__fmaf_rn(BETA, m3, a), s3f);
            s3f = (m3 > THR) ? 1.0f : 0.0f;
        }
        if (lane < Oo) {
            *p3 = s3f;
            *pm = m3;
        }

        p1 += st1; p2 += st2; p3 += st3; pm += st3;
        xa = nxa; xb = nxb;
    }
}

extern "C" void kernel_launch(void* const* d_in, const int* in_sizes, int n_in,
                              void* d_out, int out_size)
{
    const float* x  = (const float*)d_in[0];
    const float* W1 = (const float*)d_in[1];
    const float* b1 = (const float*)d_in[2];
    const float* W2 = (const float*)d_in[3];
    const float* b2 = (const float*)d_in[4];
    const float* W3 = (const float*)d_in[5];
    const float* b3 = (const float*)d_in[6];

    const int T = in_sizes[0] / (Bb * Ii);
    const size_t TB = (size_t)T * Bb;

    float* out      = (float*)d_out;
    float* out_mem3 = out;
    float* out_spk3 = out + TB * Oo;
    float* out_spk1 = out + 2 * TB * Oo;
    float* out_spk2 = out + 2 * TB * Oo + TB * H1;

    const int threads = Bb * 8;
    const int block   = 32;
    snn_kernel<<<threads / block, block>>>(x, W1, b1, W2, b2, W3, b3,
                                           out_mem3, out_spk3, out_spk1, out_spk2,
                                           T);
}

// round 6
// speedup vs baseline: 1.1085x; 1.1085x over previous
#include <cuda_runtime.h>

// TimeSeriesWineSNN: 3-layer LIF SNN, T sequential steps, B=4096.
// I=8 -> H1=28 -> H2=8 -> O=4. beta=0.9, thr=1.0 (subtract reset).
// Outputs: mem3, spk3, spk1, spk2, each [T,B,C].
//
// ONE WARP PER BATCH ELEMENT (4096 warps = 27.7 warps/SM, 4x prior occupancy).
//  L1: lane l owns channel l (l>=28: zero-pad). Spike exchange = 1 ballot.
//  L2: lane (c=l&7, u=l>>3) computes tree28 partials r[u], r[u+4] locally from
//      ballot-bit selects; final combine = 2 commutative shfl.xor hops (16, 8).
//  L3: lane (c3=l>>3, k3=l&7) holds one product; tree8 = 3 shfl.xor hops.
//  State for L2/L3 is replicated across lanes; commutativity of fp add keeps
//  replicas bit-identical.
//
// PROTECTED NUMERICS (validated r4/r5, rel_err 4.4e-9):
//  * products rounded separately (no fma); spike*w == select(bit, w, 0)
//  * tree8:  ((p0+p4)+(p2+p6)) + ((p1+p5)+(p3+p7))
//  * tree28: r[i]=(p_i+p_{i+16})+(p_{i+8}+p_{i+24}) (i<4),
//            r[i]=(p_i+p_{i+16})+p_{i+8}            (i=4..7),
//            s_i=r_i+r_{i+4}, tot=(s0+s2)+(s1+s3)
//  * epilogue: m = fma(beta, m_prev, dot + b) - s_prev ; s = (m > 1)

constexpr int   Bb  = 4096;
constexpr int   Ii  = 8;
constexpr int   H1  = 28;
constexpr int   H2  = 8;
constexpr int   Oo  = 4;
constexpr float BETA = 0.9f;
constexpr float THR  = 1.0f;

__device__ __forceinline__ float tree8_local(const float* __restrict__ p) {
    float a = __fadd_rn(__fadd_rn(p[0], p[4]), __fadd_rn(p[2], p[6]));
    float b = __fadd_rn(__fadd_rn(p[1], p[5]), __fadd_rn(p[3], p[7]));
    return __fadd_rn(a, b);
}

__device__ __forceinline__ float selbit(unsigned bt, int k, float w) {
    return ((bt >> k) & 1u) ? w : 0.0f;
}

__global__ void __launch_bounds__(128)
snn_kernel(const float* __restrict__ x,
           const float* __restrict__ W1, const float* __restrict__ b1,
           const float* __restrict__ W2, const float* __restrict__ b2,
           const float* __restrict__ W3, const float* __restrict__ b3,
           float* __restrict__ out_mem3, float* __restrict__ out_spk3,
           float* __restrict__ out_spk1, float* __restrict__ out_spk2,
           int T)
{
    const int l   = threadIdx.x & 31;                      // lane
    const int b   = (blockIdx.x * blockDim.x + threadIdx.x) >> 5;  // element
    if (b >= Bb) return;

    // ---- layer-1 weights: lane l = channel l (pad >=28 with 0) ----
    float w1r[8], b1r;
    {
        const bool real = (l < H1);
        b1r = real ? b1[l] : 0.0f;
        #pragma unroll
        for (int k = 0; k < Ii; ++k)
            w1r[k] = real ? W1[l * Ii + k] : 0.0f;
    }
    // ---- layer-2 weights: lane (c = l&7, u = l>>3) holds 7 weights ----
    const int c2 = l & 7;
    const int u  = l >> 3;
    float wa0, wa1, wa2, wa3, wb0, wb1, wb2, b2r;
    {
        const float* row = W2 + c2 * H1;
        wa0 = row[u];            // p[u]
        wa1 = row[u + 8];        // p[u+8]
        wa2 = row[u + 16];       // p[u+16]
        wa3 = (u + 24 < H1) ? row[u + 24] : 0.0f;   // u<4 always true
        wb0 = row[u + 4];        // p[u+4]
        wb1 = row[u + 12];       // p[u+12]
        wb2 = row[u + 20];       // p[u+20]
        b2r = b2[c2];
    }
    // ---- layer-3 weights: lane (c3 = l>>3, k3 = l&7) holds one ----
    const int c3 = l >> 3;      // 0..3
    const int k3 = l & 7;
    const float w3r = W3[c3 * H2 + k3];
    const float b3r = b3[c3];

    // ---- state (L2/L3 replicated across owning lanes) ----
    float m1 = 0.f, s1f = 0.f;
    float m2 = 0.f, s2f = 0.f;
    float m3 = 0.f, s3f = 0.f;

    // ---- pointers ----
    const size_t sX  = (size_t)Bb * Ii;
    const size_t st1 = (size_t)Bb * H1;
    const size_t st2 = (size_t)Bb * H2;
    const size_t st3 = (size_t)Bb * Oo;

    const float* px = x + (size_t)b * Ii;
    float* p1 = out_spk1 + (size_t)b * H1 + l;    // lanes < 28 store
    float* p2 = out_spk2 + (size_t)b * H2 + c2;   // lanes with u==0 store
    float* p3 = out_spk3 + (size_t)b * Oo + c3;   // lanes with k3==0 store
    float* pm = out_mem3 + (size_t)b * Oo + c3;

    // prefetch x[t=0] (uniform address across warp -> broadcast)
    float4 xa = *(const float4*)px;
    float4 xb = *(const float4*)(px + 4);

    #pragma unroll 2
    for (int t = 0; t < T; ++t) {
        const float* pn = px + ((t + 1 < T) ? sX : 0);
        const float4 nxa = *(const float4*)pn;
        const float4 nxb = *(const float4*)(pn + 4);
        px = pn;

        const float xk[8] = {xa.x, xa.y, xa.z, xa.w, xb.x, xb.y, xb.z, xb.w};

        // ---------- layer 1 : one channel per lane ----------
        {
            float pr[8];
            #pragma unroll
            for (int k = 0; k < Ii; ++k) pr[k] = __fmul_rn(xk[k], w1r[k]);
            float a = __fadd_rn(tree8_local(pr), b1r);
            m1  = __fsub_rn(__fmaf_rn(BETA, m1, a), s1f);
            s1f = (m1 > THR) ? 1.0f : 0.0f;
        }
        if (l < H1) *p1 = s1f;

        const unsigned bt = __ballot_sync(0xffffffffu, m1 > THR); // bit l = s1[l]

        // ---------- layer 2 : distributed tree28 ----------
        {
            // r[u]   = (p_u + p_{u+16}) + (p_{u+8} + p_{u+24})
            float rA = __fadd_rn(__fadd_rn(selbit(bt, u,      wa0),
                                           selbit(bt, u + 16, wa2)),
                                 __fadd_rn(selbit(bt, u + 8,  wa1),
                                           selbit(bt, u + 24, wa3)));
            // r[u+4] = (p_{u+4} + p_{u+20}) + p_{u+12}
            float rB = __fadd_rn(__fadd_rn(selbit(bt, u + 4,  wb0),
                                           selbit(bt, u + 20, wb2)),
                                 selbit(bt, u + 12, wb1));
            float s  = __fadd_rn(rA, rB);                       // s_u
            // (s0+s2)+(s1+s3): two commutative xor hops
            float h  = __fadd_rn(s, __shfl_xor_sync(0xffffffffu, s, 16));
            float tot= __fadd_rn(h, __shfl_xor_sync(0xffffffffu, h, 8));
            float a  = __fadd_rn(tot, b2r);
            m2  = __fsub_rn(__fmaf_rn(BETA, m2, a), s2f);
            s2f = (m2 > THR) ? 1.0f : 0.0f;
        }
        if (u == 0) *p2 = s2f;

        const unsigned bt2 = __ballot_sync(0xffffffffu, m2 > THR); // bit k (k<8) = s2[k]

        // ---------- layer 3 : distributed tree8 ----------
        {
            float p = selbit(bt2, k3, w3r);
            // ((p0+p4)+(p2+p6)) + ((p1+p5)+(p3+p7)) via xor 4,2,1
            float h1 = __fadd_rn(p,  __shfl_xor_sync(0xffffffffu, p,  4));
            float h2 = __fadd_rn(h1, __shfl_xor_sync(0xffffffffu, h1, 2));
            float tot= __fadd_rn(h2, __shfl_xor_sync(0xffffffffu, h2, 1));
            float a  = __fadd_rn(tot, b3r);
            m3  = __fsub_rn(__fmaf_rn(BETA, m3, a), s3f);
            s3f = (m3 > THR) ? 1.0f : 0.0f;
        }
        if (k3 == 0) {
            *p3 = s3f;
            *pm = m3;
        }

        p1 += st1; p2 += st2; p3 += st3; pm += st3;
        xa = nxa; xb = nxb;
    }
}

extern "C" void kernel_launch(void* const* d_in, const int* in_sizes, int n_in,
                              void* d_out, int out_size)
{
    const float* x  = (const float*)d_in[0];
    const float* W1 = (const float*)d_in[1];
    const float* b1 = (const float*)d_in[2];
    const float* W2 = (const float*)d_in[3];
    const float* b2 = (const float*)d_in[4];
    const float* W3 = (const float*)d_in[5];
    const float* b3 = (const float*)d_in[6];

    const int T = in_sizes[0] / (Bb * Ii);
    const size_t TB = (size_t)T * Bb;

    float* out      = (float*)d_out;
    float* out_mem3 = out;
    float* out_spk3 = out + TB * Oo;
    float* out_spk1 = out + 2 * TB * Oo;
    float* out_spk2 = out + 2 * TB * Oo + TB * H1;

    const int threads = Bb * 32;          // one warp per element
    const int block   = 128;
    snn_kernel<<<threads / block, block>>>(x, W1, b1, W2, b2, W3, b3,
                                           out_mem3, out_spk3, out_spk1, out_spk2,
                                           T);
}

// round 7
// speedup vs baseline: 1.3161x; 1.1873x over previous
#include <cuda_runtime.h>

// TimeSeriesWineSNN: 3-layer LIF SNN, T sequential steps, B=4096.
// I=8 -> H1=28 -> H2=8 -> O=4. beta=0.9, thr=1.0 (subtract reset).
// Outputs: mem3, spk3, spk1, spk2, each [T,B,C].
//
// One warp per batch element (4096 warps). L1: lane l = channel l.
// L2/L3 dots are functions of spike BITMASKS -> precomputed shared-mem LUTs
// holding the EXACT protected tree partial sums:
//   LUTA[u][idx4][c] = (p_u+p_{u+16}) + (p_{u+8}+p_{u+24})   (rA of tree28)
//   LUTB[u][idx3][c] = (p_{u+4}+p_{u+20}) + p_{u+12}         (rB of tree28)
//   LUT3[idx8][c3]   = full tree8 of masked W3 row
// Sub-mask extraction via carry-free multiply-gather:
//   idx4 = ((bt>>u) & 0x01010101) * 0x01020408 >> 24   (bits u,u+8,u+16,u+24)
//   idx3 = ((bt>>(u+4)) & 0x00010101) * 0x01020408 >> 24
//
// PROTECTED NUMERICS (validated r4-r6, rel_err 4.4e-9):
//  * products rounded separately (no fma); spike*w == select(bit, w, 0) == +0/w
//  * tree8:  ((p0+p4)+(p2+p6)) + ((p1+p5)+(p3+p7))
//  * tree28: r[i]=(p_i+p_{i+16})+(p_{i+8}+p_{i+24}) (i<4),
//            r[i]=(p_i+p_{i+16})+p_{i+8} (i=4..7), s_i=r_i+r_{i+4},
//            tot=(s0+s2)+(s1+s3)  [xor-shfl combine; fadd commutative]
//  * epilogue: m = fma(beta, m_prev, dot + b) - s_prev ; s = (m > 1)

constexpr int   Bb  = 4096;
constexpr int   Ii  = 8;
constexpr int   H1  = 28;
constexpr int   H2  = 8;
constexpr int   Oo  = 4;
constexpr float BETA = 0.9f;
constexpr float THR  = 1.0f;

__device__ __forceinline__ float tree8_local(const float* __restrict__ p) {
    float a = __fadd_rn(__fadd_rn(p[0], p[4]), __fadd_rn(p[2], p[6]));
    float b = __fadd_rn(__fadd_rn(p[1], p[5]), __fadd_rn(p[3], p[7]));
    return __fadd_rn(a, b);
}

__global__ void __launch_bounds__(128)
snn_kernel(const float* __restrict__ x,
           const float* __restrict__ W1, const float* __restrict__ b1,
           const float* __restrict__ W2, const float* __restrict__ b2,
           const float* __restrict__ W3, const float* __restrict__ b3,
           float* __restrict__ out_mem3, float* __restrict__ out_spk3,
           float* __restrict__ out_spk1, float* __restrict__ out_spk2,
           int T)
{
    __shared__ float lutA[4 * 16 * 8];   // [u][idx4][c2]
    __shared__ float lutB[4 * 8 * 8];    // [u][idx3][c2]
    __shared__ float lut3[256 * 4];      // [idx8][c3]

    const int tix = threadIdx.x;

    // ---- build LUTs (exact protected tree orders; +0 for masked-out) ----
    for (int e = tix; e < 4 * 16 * 8; e += 128) {        // LUTA
        const int u = e >> 7, idx = (e >> 3) & 15, c = e & 7;
        const float* row = W2 + c * H1;
        const float pa = (idx & 1) ? row[u]      : 0.0f;
        const float pb = (idx & 2) ? row[u + 8]  : 0.0f;
        const float pc = (idx & 4) ? row[u + 16] : 0.0f;
        const float pd = (idx & 8) ? row[u + 24] : 0.0f;
        lutA[e] = __fadd_rn(__fadd_rn(pa, pc), __fadd_rn(pb, pd));
    }
    for (int e = tix; e < 4 * 8 * 8; e += 128) {         // LUTB
        const int u = e >> 6, idx = (e >> 3) & 7, c = e & 7;
        const float* row = W2 + c * H1;
        const float pa = (idx & 1) ? row[u + 4]  : 0.0f;
        const float pb = (idx & 2) ? row[u + 12] : 0.0f;
        const float pc = (idx & 4) ? row[u + 20] : 0.0f;
        lutB[e] = __fadd_rn(__fadd_rn(pa, pc), pb);
    }
    for (int e = tix; e < 256 * 4; e += 128) {           // LUT3
        const int idx = e >> 2, c = e & 3;
        const float* row = W3 + c * H2;
        float p[8];
        #pragma unroll
        for (int k = 0; k < 8; ++k) p[k] = ((idx >> k) & 1) ? row[k] : 0.0f;
        lut3[e] = tree8_local(p);
    }
    __syncthreads();

    const int l = tix & 31;                               // lane
    const int b = (blockIdx.x * blockDim.x + tix) >> 5;   // batch element

    // ---- layer-1 weights: lane l = channel l (pad >=28 with 0) ----
    float w1r[8], b1r;
    {
        const bool real = (l < H1);
        b1r = real ? b1[l] : 0.0f;
        #pragma unroll
        for (int k = 0; k < Ii; ++k)
            w1r[k] = real ? W1[l * Ii + k] : 0.0f;
    }
    const int c2 = l & 7;
    const int u  = l >> 3;
    const float b2r = b2[c2];
    const int c3 = l >> 3;      // 0..3 (l>=32 impossible)
    const int k3 = l & 7;
    const float b3r = b3[c3 & 3];

    // per-lane LUT bases (u, c2 fixed)
    const float* lutAu = lutA + u * (16 * 8) + c2;
    const float* lutBu = lutB + u * (8 * 8) + c2;
    const float* lut3c = lut3 + (c3 & 3);

    // ---- state ----
    float m1 = 0.f, s1f = 0.f;
    float m2 = 0.f, s2f = 0.f;
    float m3 = 0.f, s3f = 0.f;

    // ---- pointers ----
    const size_t sX  = (size_t)Bb * Ii;
    const size_t st1 = (size_t)Bb * H1;
    const size_t st2 = (size_t)Bb * H2;
    const size_t st3 = (size_t)Bb * Oo;

    const float* px = x + (size_t)b * Ii;
    float* p1 = out_spk1 + (size_t)b * H1 + l;
    float* p2 = out_spk2 + (size_t)b * H2 + c2;
    float* p3 = out_spk3 + (size_t)b * Oo + c3;
    float* pm = out_mem3 + (size_t)b * Oo + c3;

    float4 xa = *(const float4*)px;
    float4 xb = *(const float4*)(px + 4);

    #pragma unroll 4
    for (int t = 0; t < T; ++t) {
        const float* pn = px + ((t + 1 < T) ? sX : 0);
        const float4 nxa = *(const float4*)pn;
        const float4 nxb = *(const float4*)(pn + 4);
        px = pn;

        const float xk[8] = {xa.x, xa.y, xa.z, xa.w, xb.x, xb.y, xb.z, xb.w};

        // ---------- layer 1 : one channel per lane ----------
        bool sp1;
        {
            float pr[8];
            #pragma unroll
            for (int k = 0; k < Ii; ++k) pr[k] = __fmul_rn(xk[k], w1r[k]);
            float a = __fadd_rn(tree8_local(pr), b1r);
            m1  = __fsub_rn(__fmaf_rn(BETA, m1, a), s1f);
            sp1 = (m1 > THR);
            s1f = sp1 ? 1.0f : 0.0f;
        }
        if (l < H1) *p1 = s1f;

        const unsigned bt = __ballot_sync(0xffffffffu, sp1);  // bit l = s1[l]; bits 28-31 always 0

        // ---------- layer 2 : LUT partials + 2 commutative xor hops ----------
        bool sp2;
        {
            const unsigned idxA = (((bt >> u) & 0x01010101u) * 0x01020408u) >> 24;
            const unsigned idxB = (((bt >> (u + 4)) & 0x00010101u) * 0x01020408u) >> 24;
            float s  = __fadd_rn(lutAu[idxA * 8], lutBu[idxB * 8]);   // s_u = rA + rB
            float h  = __fadd_rn(s, __shfl_xor_sync(0xffffffffu, s, 16));
            float tot= __fadd_rn(h, __shfl_xor_sync(0xffffffffu, h, 8));
            float a  = __fadd_rn(tot, b2r);
            m2  = __fsub_rn(__fmaf_rn(BETA, m2, a), s2f);
            sp2 = (m2 > THR);
            s2f = sp2 ? 1.0f : 0.0f;
        }
        if (u == 0) *p2 = s2f;

        const unsigned bt2 = __ballot_sync(0xffffffffu, sp2);  // bits 0-7 = s2 channels

        // ---------- layer 3 : single LUT lookup (uniform address) ----------
        {
            const unsigned idx = bt2 & 0xffu;
            float a = __fadd_rn(lut3c[idx * 4], b3r);
            m3  = __fsub_rn(__fmaf_rn(BETA, m3, a), s3f);
            s3f = (m3 > THR) ? 1.0f : 0.0f;
        }
        if (k3 == 0) {
            *p3 = s3f;
            *pm = m3;
        }

        p1 += st1; p2 += st2; p3 += st3; pm += st3;
        xa = nxa; xb = nxb;
    }
}

extern "C" void kernel_launch(void* const* d_in, const int* in_sizes, int n_in,
                              void* d_out, int out_size)
{
    const float* x  = (const float*)d_in[0];
    const float* W1 = (const float*)d_in[1];
    const float* b1 = (const float*)d_in[2];
    const float* W2 = (const float*)d_in[3];
    const float* b2 = (const float*)d_in[4];
    const float* W3 = (const float*)d_in[5];
    const float* b3 = (const float*)d_in[6];

    const int T = in_sizes[0] / (Bb * Ii);
    const size_t TB = (size_t)T * Bb;

    float* out      = (float*)d_out;
    float* out_mem3 = out;
    float* out_spk3 = out + TB * Oo;
    float* out_spk1 = out + 2 * TB * Oo;
    float* out_spk2 = out + 2 * TB * Oo + TB * H1;

    const int threads = Bb * 32;          // one warp per element
    const int block   = 128;
    snn_kernel<<<threads / block, block>>>(x, W1, b1, W2, b2, W3, b3,
                                           out_mem3, out_spk3, out_spk1, out_spk2,
                                           T);
}